// round 2
// baseline (speedup 1.0000x reference)
#include <cuda_runtime.h>
#include <math.h>

#define D_MODEL 1024
#define NUM_HEADS 16
#define HEAD_DIM 64
#define BATCH 2
#define SEQ 2048
#define MTOT (BATCH*SEQ)

// Scratch (allocation-free rule: __device__ globals)
__device__ float g_Q[MTOT*D_MODEL];
__device__ float g_K[MTOT*D_MODEL];
__device__ float g_V[MTOT*D_MODEL];
__device__ float g_AO[MTOT*D_MODEL];

// ---------------------------------------------------------------------------
// GEMM: C[M][N] = A[M][K] @ W[N][K]^T + bias[N]   (torch Linear convention)
// 128x128 tile, BK=16, 256 threads, 8x8 per thread.
// ---------------------------------------------------------------------------
#define GBM 128
#define GBN 128
#define GBK 16
#define GTM 8
#define GTN 8

__global__ __launch_bounds__(256, 2)
void gemm_nt_kernel(const float* __restrict__ A, const float* __restrict__ W,
                    const float* __restrict__ bias, float* __restrict__ C,
                    int M, int N, int K)
{
    __shared__ float As[GBK][GBM + 4];   // row stride 132 floats (528B, 16B-aligned)
    __shared__ float Ws[GBK][GBN + 4];

    const int tid = threadIdx.x;
    const int tx = tid & 15;
    const int ty = tid >> 4;
    const int m0 = blockIdx.y * GBM;
    const int n0 = blockIdx.x * GBN;

    float acc[GTM][GTN];
    #pragma unroll
    for (int i = 0; i < GTM; i++)
        #pragma unroll
        for (int j = 0; j < GTN; j++) acc[i][j] = 0.f;

    for (int k0 = 0; k0 < K; k0 += GBK) {
        // Load 128x16 tiles of A and W, transposed into smem [k][row]
        #pragma unroll
        for (int l = 0; l < 2; l++) {
            int id  = tid + l * 256;          // 0..511 (float4 units)
            int row = id >> 2;                // 0..127
            int kv  = id & 3;                 // 0..3 (float4 within the 16-wide k strip)
            float4 va = *reinterpret_cast<const float4*>(&A[(size_t)(m0 + row) * K + k0 + kv * 4]);
            As[kv*4+0][row] = va.x; As[kv*4+1][row] = va.y;
            As[kv*4+2][row] = va.z; As[kv*4+3][row] = va.w;
            float4 vw = *reinterpret_cast<const float4*>(&W[(size_t)(n0 + row) * K + k0 + kv * 4]);
            Ws[kv*4+0][row] = vw.x; Ws[kv*4+1][row] = vw.y;
            Ws[kv*4+2][row] = vw.z; Ws[kv*4+3][row] = vw.w;
        }
        __syncthreads();

        #pragma unroll
        for (int kk = 0; kk < GBK; kk++) {
            float a[GTM], b[GTN];
            const float4* av = reinterpret_cast<const float4*>(&As[kk][ty * GTM]);
            float4 a0 = av[0], a1 = av[1];
            a[0]=a0.x; a[1]=a0.y; a[2]=a0.z; a[3]=a0.w;
            a[4]=a1.x; a[5]=a1.y; a[6]=a1.z; a[7]=a1.w;
            const float4* bv = reinterpret_cast<const float4*>(&Ws[kk][tx * GTN]);
            float4 b0 = bv[0], b1 = bv[1];
            b[0]=b0.x; b[1]=b0.y; b[2]=b0.z; b[3]=b0.w;
            b[4]=b1.x; b[5]=b1.y; b[6]=b1.z; b[7]=b1.w;
            #pragma unroll
            for (int i = 0; i < GTM; i++)
                #pragma unroll
                for (int j = 0; j < GTN; j++)
                    acc[i][j] += a[i] * b[j];
        }
        __syncthreads();
    }

    #pragma unroll
    for (int i = 0; i < GTM; i++) {
        int row = m0 + ty * GTM + i;
        #pragma unroll
        for (int j = 0; j < GTN; j += 4) {
            int col = n0 + tx * GTN + j;
            float4 v;
            v.x = acc[i][j+0] + bias[col+0];
            v.y = acc[i][j+1] + bias[col+1];
            v.z = acc[i][j+2] + bias[col+2];
            v.w = acc[i][j+3] + bias[col+3];
            *reinterpret_cast<float4*>(&C[(size_t)row * N + col]) = v;
        }
    }
}

// ---------------------------------------------------------------------------
// Flash attention: per (b,h), 64-query tiles, iterate over 64-key tiles.
// Q/K/V are [B*S][D_MODEL]; head h occupies columns h*64..h*64+63.
// 256 threads (16x16), each thread owns a 4x4 score tile and 4x4 O tile.
// ---------------------------------------------------------------------------
#define ABM 64
#define ABN 64
#define APAD 65   // padded row length (conflict-free scalar LDS)

__global__ __launch_bounds__(256)
void attention_kernel(const float* __restrict__ Q, const float* __restrict__ K,
                      const float* __restrict__ V, float* __restrict__ O)
{
    extern __shared__ float sm[];
    float* Qs = sm;                    // 64*65
    float* Ks = Qs + ABM * APAD;
    float* Vs = Ks + ABN * APAD;
    float* Ps = Vs + ABN * APAD;

    const int tid = threadIdx.x;
    const int tx = tid & 15;
    const int ty = tid >> 4;
    const int bh = blockIdx.y;
    const int b  = bh / NUM_HEADS;
    const int h  = bh % NUM_HEADS;
    const int q0 = blockIdx.x * ABM;
    const size_t base = (size_t)b * SEQ * D_MODEL + (size_t)h * HEAD_DIM;
    const float scale = 0.125f;  // 1/sqrt(64)

    // Load Q tile (scaled). 64 rows x 16 float4, 4 per thread.
    #pragma unroll
    for (int l = 0; l < 4; l++) {
        int id  = tid + l * 256;
        int row = id >> 4;
        int c4  = id & 15;
        float4 v = *reinterpret_cast<const float4*>(&Q[base + (size_t)(q0 + row) * D_MODEL + c4 * 4]);
        float* p = &Qs[row * APAD + c4 * 4];
        p[0] = v.x * scale; p[1] = v.y * scale; p[2] = v.z * scale; p[3] = v.w * scale;
    }

    float m_i[4], l_i[4], o[4][4];
    #pragma unroll
    for (int i = 0; i < 4; i++) {
        m_i[i] = -1e30f;
        l_i[i] = 0.f;
        #pragma unroll
        for (int j = 0; j < 4; j++) o[i][j] = 0.f;
    }

    for (int kt = 0; kt < SEQ / ABN; kt++) {
        const int k0 = kt * ABN;
        // Load K and V tiles
        #pragma unroll
        for (int l = 0; l < 4; l++) {
            int id  = tid + l * 256;
            int row = id >> 4;
            int c4  = id & 15;
            size_t g = base + (size_t)(k0 + row) * D_MODEL + c4 * 4;
            float4 vk = *reinterpret_cast<const float4*>(&K[g]);
            float* pk = &Ks[row * APAD + c4 * 4];
            pk[0]=vk.x; pk[1]=vk.y; pk[2]=vk.z; pk[3]=vk.w;
            float4 vv = *reinterpret_cast<const float4*>(&V[g]);
            float* pv = &Vs[row * APAD + c4 * 4];
            pv[0]=vv.x; pv[1]=vv.y; pv[2]=vv.z; pv[3]=vv.w;
        }
        __syncthreads();

        // S = Qs @ Ks^T (dot over d)
        float s[4][4];
        #pragma unroll
        for (int i = 0; i < 4; i++)
            #pragma unroll
            for (int j = 0; j < 4; j++) s[i][j] = 0.f;
        #pragma unroll 4
        for (int d = 0; d < HEAD_DIM; d++) {
            float qa[4], kb[4];
            #pragma unroll
            for (int i = 0; i < 4; i++) qa[i] = Qs[(ty*4+i) * APAD + d];
            #pragma unroll
            for (int j = 0; j < 4; j++) kb[j] = Ks[(tx*4+j) * APAD + d];
            #pragma unroll
            for (int i = 0; i < 4; i++)
                #pragma unroll
                for (int j = 0; j < 4; j++)
                    s[i][j] += qa[i] * kb[j];
        }

        // Online softmax: row reductions across the 16 tx-lanes (same half-warp)
        float alpha[4];
        #pragma unroll
        for (int i = 0; i < 4; i++) {
            float mloc = fmaxf(fmaxf(s[i][0], s[i][1]), fmaxf(s[i][2], s[i][3]));
            #pragma unroll
            for (int off = 8; off >= 1; off >>= 1)
                mloc = fmaxf(mloc, __shfl_xor_sync(0xffffffffu, mloc, off));
            float m_new = fmaxf(m_i[i], mloc);
            alpha[i] = __expf(m_i[i] - m_new);
            float rs = 0.f;
            #pragma unroll
            for (int j = 0; j < 4; j++) {
                float p = __expf(s[i][j] - m_new);
                s[i][j] = p;
                rs += p;
            }
            #pragma unroll
            for (int off = 8; off >= 1; off >>= 1)
                rs += __shfl_xor_sync(0xffffffffu, rs, off);
            l_i[i] = alpha[i] * l_i[i] + rs;
            m_i[i] = m_new;
            // rescale O accumulator
            #pragma unroll
            for (int j = 0; j < 4; j++) o[i][j] *= alpha[i];
            // stash P
            #pragma unroll
            for (int j = 0; j < 4; j++)
                Ps[(ty*4+i) * APAD + tx*4 + j] = s[i][j];
        }
        __syncthreads();

        // O += P @ V
        #pragma unroll 4
        for (int kk = 0; kk < ABN; kk++) {
            float pa[4], vb[4];
            #pragma unroll
            for (int i = 0; i < 4; i++) pa[i] = Ps[(ty*4+i) * APAD + kk];
            #pragma unroll
            for (int j = 0; j < 4; j++) vb[j] = Vs[kk * APAD + tx*4 + j];
            #pragma unroll
            for (int i = 0; i < 4; i++)
                #pragma unroll
                for (int j = 0; j < 4; j++)
                    o[i][j] += pa[i] * vb[j];
        }
        __syncthreads();  // protect Ks/Vs/Ps before next iteration overwrites
    }

    // Normalize and write out: O[b*S + q0+row][h*64 + col]
    #pragma unroll
    for (int i = 0; i < 4; i++) {
        float inv = 1.0f / l_i[i];
        float4 v;
        v.x = o[i][0] * inv; v.y = o[i][1] * inv;
        v.z = o[i][2] * inv; v.w = o[i][3] * inv;
        *reinterpret_cast<float4*>(&O[base + (size_t)(q0 + ty*4 + i) * D_MODEL + tx*4]) = v;
    }
}

// ---------------------------------------------------------------------------
extern "C" void kernel_launch(void* const* d_in, const int* in_sizes, int n_in,
                              void* d_out, int out_size)
{
    const float* x  = (const float*)d_in[0];
    const float* Wq = (const float*)d_in[1];
    const float* bq = (const float*)d_in[2];
    const float* Wk = (const float*)d_in[3];
    const float* bk = (const float*)d_in[4];
    const float* Wv = (const float*)d_in[5];
    const float* bv = (const float*)d_in[6];
    const float* Wo = (const float*)d_in[7];
    const float* bo = (const float*)d_in[8];
    float* out = (float*)d_out;

    float *Qp, *Kp, *Vp, *Op;
    cudaGetSymbolAddress((void**)&Qp, g_Q);
    cudaGetSymbolAddress((void**)&Kp, g_K);
    cudaGetSymbolAddress((void**)&Vp, g_V);
    cudaGetSymbolAddress((void**)&Op, g_AO);

    const int M = MTOT, N = D_MODEL, K = D_MODEL;
    dim3 ggrid(N / GBN, M / GBM);   // (8, 32)
    dim3 gblk(256);

    gemm_nt_kernel<<<ggrid, gblk>>>(x, Wq, bq, Qp, M, N, K);
    gemm_nt_kernel<<<ggrid, gblk>>>(x, Wk, bk, Kp, M, N, K);
    gemm_nt_kernel<<<ggrid, gblk>>>(x, Wv, bv, Vp, M, N, K);

    const int smem = 4 * ABM * APAD * sizeof(float);  // 66560 B
    cudaFuncSetAttribute(attention_kernel, cudaFuncAttributeMaxDynamicSharedMemorySize, smem);
    dim3 agrid(SEQ / ABM, BATCH * NUM_HEADS);         // (32, 32)
    attention_kernel<<<agrid, 256, smem>>>(Qp, Kp, Vp, Op);

    gemm_nt_kernel<<<ggrid, gblk>>>(Op, Wo, bo, out, M, N, K);
}

// round 11
// speedup vs baseline: 1.2883x; 1.2883x over previous
#include <cuda_runtime.h>
#include <cuda_bf16.h>
#include <cstdint>
#include <math.h>

#define D_MODEL 1024
#define NUM_HEADS 16
#define HEAD_DIM 64
#define BATCH 2
#define SEQ 2048
#define MTOT (BATCH*SEQ)

typedef __nv_bfloat16 bf16;
typedef __nv_bfloat162 bf162;

// ---------------------------------------------------------------------------
// Scratch (allocation-free rule: __device__ globals)
// ---------------------------------------------------------------------------
__device__ float g_Q[MTOT*D_MODEL];
__device__ float g_K[MTOT*D_MODEL];
__device__ float g_V[MTOT*D_MODEL];
__device__ float g_AO[MTOT*D_MODEL];

__device__ bf16 g_xhi[MTOT*D_MODEL];
__device__ bf16 g_xlo[MTOT*D_MODEL];
__device__ bf16 g_aohi[MTOT*D_MODEL];
__device__ bf16 g_aolo[MTOT*D_MODEL];
__device__ bf16 g_whi[D_MODEL*D_MODEL];
__device__ bf16 g_wlo[D_MODEL*D_MODEL];

// ---------------------------------------------------------------------------
// Standard-PTX helpers (sm_80-era; valid for compute_103 virtual arch)
// ---------------------------------------------------------------------------
__device__ __forceinline__ uint32_t smem_u32(const void* p) {
    uint32_t a;
    asm("{ .reg .u64 t; cvta.to.shared.u64 t, %1; cvt.u32.u64 %0, t; }" : "=r"(a) : "l"(p));
    return a;
}
__device__ __forceinline__ void ldsm4(uint32_t r[4], uint32_t a) {
    asm volatile("ldmatrix.sync.aligned.m8n8.x4.shared.b16 {%0,%1,%2,%3}, [%4];"
                 : "=r"(r[0]), "=r"(r[1]), "=r"(r[2]), "=r"(r[3]) : "r"(a));
}
__device__ __forceinline__ void mma_bf16(float c[4], const uint32_t a[4], const uint32_t b[2]) {
    asm volatile("mma.sync.aligned.m16n8k16.row.col.f32.bf16.bf16.f32 "
                 "{%0,%1,%2,%3}, {%4,%5,%6,%7}, {%8,%9}, {%0,%1,%2,%3};"
                 : "+f"(c[0]), "+f"(c[1]), "+f"(c[2]), "+f"(c[3])
                 : "r"(a[0]), "r"(a[1]), "r"(a[2]), "r"(a[3]), "r"(b[0]), "r"(b[1]));
}
__device__ __forceinline__ void cp16(uint32_t s, const void* g) {
    asm volatile("cp.async.cg.shared.global [%0], [%1], 16;" :: "r"(s), "l"(g) : "memory");
}
#define CP_COMMIT() asm volatile("cp.async.commit_group;" ::: "memory")
#define CP_WAIT1()  asm volatile("cp.async.wait_group 1;" ::: "memory")
#define CP_WAIT0()  asm volatile("cp.async.wait_group 0;" ::: "memory")

__device__ __forceinline__ uint32_t pack_split(float v0, float v1, uint32_t& lo_out) {
    bf162 h, l;
    h.x = __float2bfloat16(v0); h.y = __float2bfloat16(v1);
    l.x = __float2bfloat16(v0 - __bfloat162float(h.x));
    l.y = __float2bfloat16(v1 - __bfloat162float(h.y));
    lo_out = *reinterpret_cast<uint32_t*>(&l);
    return *reinterpret_cast<uint32_t*>(&h);
}

// ---------------------------------------------------------------------------
// Split: fp32 -> bf16 hi + bf16 lo
// ---------------------------------------------------------------------------
__global__ void split_kernel(const float* __restrict__ x,
                             bf16* __restrict__ hi, bf16* __restrict__ lo, int n4)
{
    int i = blockIdx.x * blockDim.x + threadIdx.x;
    if (i >= n4) return;
    float4 v = reinterpret_cast<const float4*>(x)[i];
    uint2 hu, lu;
    hu.x = pack_split(v.x, v.y, lu.x);
    hu.y = pack_split(v.z, v.w, lu.y);
    reinterpret_cast<uint2*>(hi)[i] = hu;
    reinterpret_cast<uint2*>(lo)[i] = lu;
}

// ---------------------------------------------------------------------------
// Tensor-core GEMM via mma.sync: C[4096][1024] = A @ W^T + bias (fp32 out)
// bf16 2-split, 3 MMA terms, fp32 HMMA accumulators.
// CTA 128x128, BK=32, KTILES=32 (full K=1024!), 8 warps, cp.async dbl buffer.
// ---------------------------------------------------------------------------
#define BKP 40                     // padded smem row stride (bf16 units)
#define G_ASTG 20480               // per-stage bytes (hi+lo: 2*128*40*2)
#define G_SMEM (4 * G_ASTG)        // 81920
#define KTILES 32                  // 32 * BK(32) = 1024 = D_MODEL

__global__ __launch_bounds__(256, 1)
void gemm_tc(const bf16* __restrict__ Ahi, const bf16* __restrict__ Alo,
             const bf16* __restrict__ Whi, const bf16* __restrict__ Wlo,
             const float* __restrict__ bias, float* __restrict__ Cf)
{
    extern __shared__ __align__(128) char smem[];
    const uint32_t sb = smem_u32(smem);
    const int tid = threadIdx.x;
    const int L = tid & 31, w = tid >> 5;
    const int wm = w >> 2, wn = w & 3;
    const int m0 = blockIdx.y * 128, n0 = blockIdx.x * 128;

    float acc[4][4][4];
    #pragma unroll
    for (int i = 0; i < 4; i++)
        #pragma unroll
        for (int j = 0; j < 4; j++)
            #pragma unroll
            for (int c = 0; c < 4; c++) acc[i][j][c] = 0.f;

    auto load_stage = [&](int kt) {
        const int s = kt & 1, k0 = kt * 32;
        const uint32_t aof = sb + s * G_ASTG;
        const uint32_t wof = sb + 2 * G_ASTG + s * G_ASTG;
        #pragma unroll
        for (int l = 0; l < 2; l++) {
            int id = tid + l * 256;
            int row = id >> 2, c = id & 3;
            uint32_t so = (uint32_t)(row * BKP + c * 8) * 2;
            size_t gA = (size_t)(m0 + row) * D_MODEL + k0 + c * 8;
            cp16(aof + so, Ahi + gA);
            cp16(aof + 10240 + so, Alo + gA);
            size_t gW = (size_t)(n0 + row) * D_MODEL + k0 + c * 8;
            cp16(wof + so, Whi + gW);
            cp16(wof + 10240 + so, Wlo + gW);
        }
        CP_COMMIT();
    };

    load_stage(0);
    for (int kt = 0; kt < KTILES; kt++) {
        const int s = kt & 1;
        if (kt + 1 < KTILES) { load_stage(kt + 1); CP_WAIT1(); } else { CP_WAIT0(); }
        __syncthreads();
        const uint32_t aof = sb + s * G_ASTG;
        const uint32_t wof = sb + 2 * G_ASTG + s * G_ASTG;

        #pragma unroll
        for (int ks = 0; ks < 2; ks++) {
            uint32_t a_hi[4][4], a_lo[4][4];
            #pragma unroll
            for (int i = 0; i < 4; i++) {
                int row = wm * 64 + i * 16 + (L & 15);
                int col = ks * 16 + ((L >> 4) & 1) * 8;
                uint32_t off = (uint32_t)(row * BKP + col) * 2;
                ldsm4(a_hi[i], aof + off);
                ldsm4(a_lo[i], aof + 10240 + off);
            }
            uint32_t b_hi[4][2], b_lo[4][2];
            #pragma unroll
            for (int p = 0; p < 2; p++) {
                int nrow = wn * 32 + p * 16 + (L & 7) + ((L >> 4) & 1) * 8;
                int col = ks * 16 + ((L >> 3) & 1) * 8;
                uint32_t off = (uint32_t)(nrow * BKP + col) * 2;
                uint32_t r[4];
                ldsm4(r, wof + off);
                b_hi[2*p][0] = r[0]; b_hi[2*p][1] = r[1];
                b_hi[2*p+1][0] = r[2]; b_hi[2*p+1][1] = r[3];
                ldsm4(r, wof + 10240 + off);
                b_lo[2*p][0] = r[0]; b_lo[2*p][1] = r[1];
                b_lo[2*p+1][0] = r[2]; b_lo[2*p+1][1] = r[3];
            }
            #pragma unroll
            for (int i = 0; i < 4; i++)
                #pragma unroll
                for (int j = 0; j < 4; j++) {
                    mma_bf16(acc[i][j], a_hi[i], b_hi[j]);
                    mma_bf16(acc[i][j], a_hi[i], b_lo[j]);
                    mma_bf16(acc[i][j], a_lo[i], b_hi[j]);
                }
        }
        __syncthreads();
    }

    // epilogue: fp32 + bias
    #pragma unroll
    for (int i = 0; i < 4; i++) {
        int rg = m0 + wm * 64 + i * 16 + (L >> 2);
        #pragma unroll
        for (int j = 0; j < 4; j++) {
            int col = n0 + wn * 32 + j * 8 + 2 * (L & 3);
            float b0v = bias[col], b1v = bias[col + 1];
            float2 v0 = { acc[i][j][0] + b0v, acc[i][j][1] + b1v };
            float2 v1 = { acc[i][j][2] + b0v, acc[i][j][3] + b1v };
            *reinterpret_cast<float2*>(&Cf[(size_t)rg * D_MODEL + col]) = v0;
            *reinterpret_cast<float2*>(&Cf[(size_t)(rg + 8) * D_MODEL + col]) = v1;
        }
    }
}

// ---------------------------------------------------------------------------
// Flash attention (fp32 CUDA cores) — VERBATIM from the proven R1 kernel.
// ---------------------------------------------------------------------------
#define ABM 64
#define ABN 64
#define APAD 65

__global__ __launch_bounds__(256)
void attention_kernel(const float* __restrict__ Q, const float* __restrict__ K,
                      const float* __restrict__ V, float* __restrict__ O)
{
    extern __shared__ float sm[];
    float* Qs = sm;
    float* Ks = Qs + ABM * APAD;
    float* Vs = Ks + ABN * APAD;
    float* Ps = Vs + ABN * APAD;

    const int tid = threadIdx.x;
    const int tx = tid & 15;
    const int ty = tid >> 4;
    const int bh = blockIdx.y;
    const int b  = bh / NUM_HEADS;
    const int h  = bh % NUM_HEADS;
    const int q0 = blockIdx.x * ABM;
    const size_t base = (size_t)b * SEQ * D_MODEL + (size_t)h * HEAD_DIM;
    const float scale = 0.125f;

    #pragma unroll
    for (int l = 0; l < 4; l++) {
        int id  = tid + l * 256;
        int row = id >> 4;
        int c4  = id & 15;
        float4 v = *reinterpret_cast<const float4*>(&Q[base + (size_t)(q0 + row) * D_MODEL + c4 * 4]);
        float* p = &Qs[row * APAD + c4 * 4];
        p[0] = v.x * scale; p[1] = v.y * scale; p[2] = v.z * scale; p[3] = v.w * scale;
    }

    float m_i[4], l_i[4], o[4][4];
    #pragma unroll
    for (int i = 0; i < 4; i++) {
        m_i[i] = -1e30f;
        l_i[i] = 0.f;
        #pragma unroll
        for (int j = 0; j < 4; j++) o[i][j] = 0.f;
    }

    for (int kt = 0; kt < SEQ / ABN; kt++) {
        const int k0 = kt * ABN;
        #pragma unroll
        for (int l = 0; l < 4; l++) {
            int id  = tid + l * 256;
            int row = id >> 4;
            int c4  = id & 15;
            size_t g = base + (size_t)(k0 + row) * D_MODEL + c4 * 4;
            float4 vk = *reinterpret_cast<const float4*>(&K[g]);
            float* pk = &Ks[row * APAD + c4 * 4];
            pk[0]=vk.x; pk[1]=vk.y; pk[2]=vk.z; pk[3]=vk.w;
            float4 vv = *reinterpret_cast<const float4*>(&V[g]);
            float* pv = &Vs[row * APAD + c4 * 4];
            pv[0]=vv.x; pv[1]=vv.y; pv[2]=vv.z; pv[3]=vv.w;
        }
        __syncthreads();

        float s[4][4];
        #pragma unroll
        for (int i = 0; i < 4; i++)
            #pragma unroll
            for (int j = 0; j < 4; j++) s[i][j] = 0.f;
        #pragma unroll 4
        for (int d = 0; d < HEAD_DIM; d++) {
            float qa[4], kb[4];
            #pragma unroll
            for (int i = 0; i < 4; i++) qa[i] = Qs[(ty*4+i) * APAD + d];
            #pragma unroll
            for (int j = 0; j < 4; j++) kb[j] = Ks[(tx*4+j) * APAD + d];
            #pragma unroll
            for (int i = 0; i < 4; i++)
                #pragma unroll
                for (int j = 0; j < 4; j++)
                    s[i][j] += qa[i] * kb[j];
        }

        float alpha[4];
        #pragma unroll
        for (int i = 0; i < 4; i++) {
            float mloc = fmaxf(fmaxf(s[i][0], s[i][1]), fmaxf(s[i][2], s[i][3]));
            #pragma unroll
            for (int off = 8; off >= 1; off >>= 1)
                mloc = fmaxf(mloc, __shfl_xor_sync(0xffffffffu, mloc, off));
            float m_new = fmaxf(m_i[i], mloc);
            alpha[i] = __expf(m_i[i] - m_new);
            float rs = 0.f;
            #pragma unroll
            for (int j = 0; j < 4; j++) {
                float p = __expf(s[i][j] - m_new);
                s[i][j] = p;
                rs += p;
            }
            #pragma unroll
            for (int off = 8; off >= 1; off >>= 1)
                rs += __shfl_xor_sync(0xffffffffu, rs, off);
            l_i[i] = alpha[i] * l_i[i] + rs;
            m_i[i] = m_new;
            #pragma unroll
            for (int j = 0; j < 4; j++) o[i][j] *= alpha[i];
            #pragma unroll
            for (int j = 0; j < 4; j++)
                Ps[(ty*4+i) * APAD + tx*4 + j] = s[i][j];
        }
        __syncthreads();

        #pragma unroll 4
        for (int kk = 0; kk < ABN; kk++) {
            float pa[4], vb[4];
            #pragma unroll
            for (int i = 0; i < 4; i++) pa[i] = Ps[(ty*4+i) * APAD + kk];
            #pragma unroll
            for (int j = 0; j < 4; j++) vb[j] = Vs[kk * APAD + tx*4 + j];
            #pragma unroll
            for (int i = 0; i < 4; i++)
                #pragma unroll
                for (int j = 0; j < 4; j++)
                    o[i][j] += pa[i] * vb[j];
        }
        __syncthreads();
    }

    #pragma unroll
    for (int i = 0; i < 4; i++) {
        float inv = 1.0f / l_i[i];
        float4 v;
        v.x = o[i][0] * inv; v.y = o[i][1] * inv;
        v.z = o[i][2] * inv; v.w = o[i][3] * inv;
        *reinterpret_cast<float4*>(&O[base + (size_t)(q0 + ty*4 + i) * D_MODEL + tx*4]) = v;
    }
}

// ---------------------------------------------------------------------------
extern "C" void kernel_launch(void* const* d_in, const int* in_sizes, int n_in,
                              void* d_out, int out_size)
{
    const float* x  = (const float*)d_in[0];
    const float* Wq = (const float*)d_in[1];
    const float* bq = (const float*)d_in[2];
    const float* Wk = (const float*)d_in[3];
    const float* bk = (const float*)d_in[4];
    const float* Wv = (const float*)d_in[5];
    const float* bv = (const float*)d_in[6];
    const float* Wo = (const float*)d_in[7];
    const float* bo = (const float*)d_in[8];
    float* out = (float*)d_out;

    float *Qp, *Kp, *Vp, *Op;
    bf16 *xhi, *xlo, *aohi, *aolo, *whi, *wlo;
    cudaGetSymbolAddress((void**)&Qp, g_Q);
    cudaGetSymbolAddress((void**)&Kp, g_K);
    cudaGetSymbolAddress((void**)&Vp, g_V);
    cudaGetSymbolAddress((void**)&Op, g_AO);
    cudaGetSymbolAddress((void**)&xhi, g_xhi);
    cudaGetSymbolAddress((void**)&xlo, g_xlo);
    cudaGetSymbolAddress((void**)&aohi, g_aohi);
    cudaGetSymbolAddress((void**)&aolo, g_aolo);
    cudaGetSymbolAddress((void**)&whi, g_whi);
    cudaGetSymbolAddress((void**)&wlo, g_wlo);

    cudaFuncSetAttribute(gemm_tc, cudaFuncAttributeMaxDynamicSharedMemorySize, G_SMEM);
    const int att_smem = 4 * ABM * APAD * sizeof(float);  // 66560
    cudaFuncSetAttribute(attention_kernel, cudaFuncAttributeMaxDynamicSharedMemorySize, att_smem);

    const int nx4 = MTOT * D_MODEL / 4;
    const int nw4 = D_MODEL * D_MODEL / 4;
    dim3 ggrid(D_MODEL / 128, MTOT / 128);   // (8, 32)

    // split input activations once
    split_kernel<<<nx4 / 256, 256>>>(x, xhi, xlo, nx4);

    // Q/K/V projections on tensor cores (fp32 outputs)
    split_kernel<<<nw4 / 256, 256>>>(Wq, whi, wlo, nw4);
    gemm_tc<<<ggrid, 256, G_SMEM>>>(xhi, xlo, whi, wlo, bq, Qp);
    split_kernel<<<nw4 / 256, 256>>>(Wk, whi, wlo, nw4);
    gemm_tc<<<ggrid, 256, G_SMEM>>>(xhi, xlo, whi, wlo, bk, Kp);
    split_kernel<<<nw4 / 256, 256>>>(Wv, whi, wlo, nw4);
    gemm_tc<<<ggrid, 256, G_SMEM>>>(xhi, xlo, whi, wlo, bv, Vp);

    // attention (proven fp32 kernel)
    dim3 agrid(SEQ / ABM, BATCH * NUM_HEADS);  // (32, 32)
    attention_kernel<<<agrid, 256, att_smem>>>(Qp, Kp, Vp, Op);

    // output projection on tensor cores
    split_kernel<<<nx4 / 256, 256>>>(Op, aohi, aolo, nx4);
    split_kernel<<<nw4 / 256, 256>>>(Wo, whi, wlo, nw4);
    gemm_tc<<<ggrid, 256, G_SMEM>>>(aohi, aolo, whi, wlo, bo, out);
}

// round 17
// speedup vs baseline: 2.7090x; 2.1028x over previous
#include <cuda_runtime.h>
#include <cuda_bf16.h>
#include <cstdint>
#include <math.h>

#define D_MODEL 1024
#define NUM_HEADS 16
#define HEAD_DIM 64
#define BATCH 2
#define SEQ 2048
#define MTOT (BATCH*SEQ)

typedef __nv_bfloat16 bf16;
typedef __nv_bfloat162 bf162;

// ---------------------------------------------------------------------------
// Scratch (allocation-free rule: __device__ globals)
// ---------------------------------------------------------------------------
__device__ float g_Q[MTOT*D_MODEL];
__device__ float g_K[MTOT*D_MODEL];
__device__ float g_V[MTOT*D_MODEL];
__device__ float g_AO[MTOT*D_MODEL];

__device__ bf16 g_xhi[MTOT*D_MODEL];
__device__ bf16 g_xlo[MTOT*D_MODEL];
__device__ bf16 g_aohi[MTOT*D_MODEL];
__device__ bf16 g_aolo[MTOT*D_MODEL];
__device__ bf16 g_whi[D_MODEL*D_MODEL];
__device__ bf16 g_wlo[D_MODEL*D_MODEL];
__device__ bf16 g_qhi[MTOT*D_MODEL];
__device__ bf16 g_qlo[MTOT*D_MODEL];
__device__ bf16 g_khi[MTOT*D_MODEL];
__device__ bf16 g_klo[MTOT*D_MODEL];
__device__ bf16 g_vhi[MTOT*D_MODEL];
__device__ bf16 g_vlo[MTOT*D_MODEL];

// ---------------------------------------------------------------------------
// Standard-PTX helpers (sm_80-era; valid for compute_103 virtual arch)
// ---------------------------------------------------------------------------
__device__ __forceinline__ uint32_t smem_u32(const void* p) {
    uint32_t a;
    asm("{ .reg .u64 t; cvta.to.shared.u64 t, %1; cvt.u32.u64 %0, t; }" : "=r"(a) : "l"(p));
    return a;
}
__device__ __forceinline__ void ldsm4(uint32_t r[4], uint32_t a) {
    asm volatile("ldmatrix.sync.aligned.m8n8.x4.shared.b16 {%0,%1,%2,%3}, [%4];"
                 : "=r"(r[0]), "=r"(r[1]), "=r"(r[2]), "=r"(r[3]) : "r"(a));
}
__device__ __forceinline__ void ldsm4t(uint32_t r[4], uint32_t a) {
    asm volatile("ldmatrix.sync.aligned.m8n8.x4.trans.shared.b16 {%0,%1,%2,%3}, [%4];"
                 : "=r"(r[0]), "=r"(r[1]), "=r"(r[2]), "=r"(r[3]) : "r"(a));
}
__device__ __forceinline__ void mma_bf16(float c[4], const uint32_t a[4], const uint32_t b[2]) {
    asm volatile("mma.sync.aligned.m16n8k16.row.col.f32.bf16.bf16.f32 "
                 "{%0,%1,%2,%3}, {%4,%5,%6,%7}, {%8,%9}, {%0,%1,%2,%3};"
                 : "+f"(c[0]), "+f"(c[1]), "+f"(c[2]), "+f"(c[3])
                 : "r"(a[0]), "r"(a[1]), "r"(a[2]), "r"(a[3]), "r"(b[0]), "r"(b[1]));
}
__device__ __forceinline__ void cp16(uint32_t s, const void* g) {
    asm volatile("cp.async.cg.shared.global [%0], [%1], 16;" :: "r"(s), "l"(g) : "memory");
}
#define CP_COMMIT() asm volatile("cp.async.commit_group;" ::: "memory")
#define CP_WAIT1()  asm volatile("cp.async.wait_group 1;" ::: "memory")
#define CP_WAIT0()  asm volatile("cp.async.wait_group 0;" ::: "memory")

__device__ __forceinline__ uint32_t pack_split(float v0, float v1, uint32_t& lo_out) {
    bf162 h, l;
    h.x = __float2bfloat16(v0); h.y = __float2bfloat16(v1);
    l.x = __float2bfloat16(v0 - __bfloat162float(h.x));
    l.y = __float2bfloat16(v1 - __bfloat162float(h.y));
    lo_out = *reinterpret_cast<uint32_t*>(&l);
    return *reinterpret_cast<uint32_t*>(&h);
}

// ---------------------------------------------------------------------------
// Split: fp32 -> (scale*) bf16 hi + bf16 lo
// ---------------------------------------------------------------------------
__global__ void split_kernel(const float* __restrict__ x,
                             bf16* __restrict__ hi, bf16* __restrict__ lo,
                             int n4, float scale)
{
    int i = blockIdx.x * blockDim.x + threadIdx.x;
    if (i >= n4) return;
    float4 v = reinterpret_cast<const float4*>(x)[i];
    uint2 hu, lu;
    hu.x = pack_split(v.x * scale, v.y * scale, lu.x);
    hu.y = pack_split(v.z * scale, v.w * scale, lu.y);
    reinterpret_cast<uint2*>(hi)[i] = hu;
    reinterpret_cast<uint2*>(lo)[i] = lu;
}

// ---------------------------------------------------------------------------
// Tensor-core GEMM (VALIDATED R11): C[4096][1024] = A @ W^T + bias (fp32 out)
// ---------------------------------------------------------------------------
#define BKP 40
#define G_ASTG 20480
#define G_SMEM (4 * G_ASTG)
#define KTILES 32

__global__ __launch_bounds__(256, 1)
void gemm_tc(const bf16* __restrict__ Ahi, const bf16* __restrict__ Alo,
             const bf16* __restrict__ Whi, const bf16* __restrict__ Wlo,
             const float* __restrict__ bias, float* __restrict__ Cf)
{
    extern __shared__ __align__(128) char smem[];
    const uint32_t sb = smem_u32(smem);
    const int tid = threadIdx.x;
    const int L = tid & 31, w = tid >> 5;
    const int wm = w >> 2, wn = w & 3;
    const int m0 = blockIdx.y * 128, n0 = blockIdx.x * 128;

    float acc[4][4][4];
    #pragma unroll
    for (int i = 0; i < 4; i++)
        #pragma unroll
        for (int j = 0; j < 4; j++)
            #pragma unroll
            for (int c = 0; c < 4; c++) acc[i][j][c] = 0.f;

    auto load_stage = [&](int kt) {
        const int s = kt & 1, k0 = kt * 32;
        const uint32_t aof = sb + s * G_ASTG;
        const uint32_t wof = sb + 2 * G_ASTG + s * G_ASTG;
        #pragma unroll
        for (int l = 0; l < 2; l++) {
            int id = tid + l * 256;
            int row = id >> 2, c = id & 3;
            uint32_t so = (uint32_t)(row * BKP + c * 8) * 2;
            size_t gA = (size_t)(m0 + row) * D_MODEL + k0 + c * 8;
            cp16(aof + so, Ahi + gA);
            cp16(aof + 10240 + so, Alo + gA);
            size_t gW = (size_t)(n0 + row) * D_MODEL + k0 + c * 8;
            cp16(wof + so, Whi + gW);
            cp16(wof + 10240 + so, Wlo + gW);
        }
        CP_COMMIT();
    };

    load_stage(0);
    for (int kt = 0; kt < KTILES; kt++) {
        const int s = kt & 1;
        if (kt + 1 < KTILES) { load_stage(kt + 1); CP_WAIT1(); } else { CP_WAIT0(); }
        __syncthreads();
        const uint32_t aof = sb + s * G_ASTG;
        const uint32_t wof = sb + 2 * G_ASTG + s * G_ASTG;

        #pragma unroll
        for (int ks = 0; ks < 2; ks++) {
            uint32_t a_hi[4][4], a_lo[4][4];
            #pragma unroll
            for (int i = 0; i < 4; i++) {
                int row = wm * 64 + i * 16 + (L & 15);
                int col = ks * 16 + ((L >> 4) & 1) * 8;
                uint32_t off = (uint32_t)(row * BKP + col) * 2;
                ldsm4(a_hi[i], aof + off);
                ldsm4(a_lo[i], aof + 10240 + off);
            }
            uint32_t b_hi[4][2], b_lo[4][2];
            #pragma unroll
            for (int p = 0; p < 2; p++) {
                int nrow = wn * 32 + p * 16 + (L & 7) + ((L >> 4) & 1) * 8;
                int col = ks * 16 + ((L >> 3) & 1) * 8;
                uint32_t off = (uint32_t)(nrow * BKP + col) * 2;
                uint32_t r[4];
                ldsm4(r, wof + off);
                b_hi[2*p][0] = r[0]; b_hi[2*p][1] = r[1];
                b_hi[2*p+1][0] = r[2]; b_hi[2*p+1][1] = r[3];
                ldsm4(r, wof + 10240 + off);
                b_lo[2*p][0] = r[0]; b_lo[2*p][1] = r[1];
                b_lo[2*p+1][0] = r[2]; b_lo[2*p+1][1] = r[3];
            }
            #pragma unroll
            for (int i = 0; i < 4; i++)
                #pragma unroll
                for (int j = 0; j < 4; j++) {
                    mma_bf16(acc[i][j], a_hi[i], b_hi[j]);
                    mma_bf16(acc[i][j], a_hi[i], b_lo[j]);
                    mma_bf16(acc[i][j], a_lo[i], b_hi[j]);
                }
        }
        __syncthreads();
    }

    #pragma unroll
    for (int i = 0; i < 4; i++) {
        int rg = m0 + wm * 64 + i * 16 + (L >> 2);
        #pragma unroll
        for (int j = 0; j < 4; j++) {
            int col = n0 + wn * 32 + j * 8 + 2 * (L & 3);
            float b0v = bias[col], b1v = bias[col + 1];
            float2 v0 = { acc[i][j][0] + b0v, acc[i][j][1] + b1v };
            float2 v1 = { acc[i][j][2] + b0v, acc[i][j][3] + b1v };
            *reinterpret_cast<float2*>(&Cf[(size_t)rg * D_MODEL + col]) = v0;
            *reinterpret_cast<float2*>(&Cf[(size_t)(rg + 8) * D_MODEL + col]) = v1;
        }
    }
}

// ---------------------------------------------------------------------------
// Flash attention via mma.sync. 128-query tiles, 8 warps x 16 rows.
// K-tiles of 64 keys, cp.async double-buffered. bf16 2-split operands.
// qhi/qlo arrive pre-scaled by 1/sqrt(Dh). Output: fp32 O.
// ---------------------------------------------------------------------------
#define VP 72                       // padded smem row stride (bf16 units)
#define A_QBYTES 18432              // 128*72*2
#define A_KVQ 9216                  // 64*72*2
#define A_STG 36864                 // K hi/lo + V hi/lo per stage
#define A_SMEM (2 * A_QBYTES + 2 * A_STG)   // 110592

__global__ __launch_bounds__(256, 1)
void attn_tc(const bf16* __restrict__ qhi, const bf16* __restrict__ qlo,
             const bf16* __restrict__ khi, const bf16* __restrict__ klo,
             const bf16* __restrict__ vhi, const bf16* __restrict__ vlo,
             float* __restrict__ O)
{
    extern __shared__ __align__(128) char smem[];
    const uint32_t sb = smem_u32(smem);
    const uint32_t QH = sb, QL = sb + A_QBYTES;
    const int tid = threadIdx.x;
    const int L = tid & 31, w = tid >> 5;
    const int q0 = blockIdx.x * 128;
    const int b = blockIdx.y >> 4, h = blockIdx.y & 15;
    const size_t rowbase = (size_t)b * SEQ * D_MODEL + (size_t)h * HEAD_DIM;

    auto load_kv = [&](int kt) {
        const int s = kt & 1, k0 = kt * 64;
        const uint32_t st = sb + 2 * A_QBYTES + s * A_STG;
        #pragma unroll
        for (int l = 0; l < 2; l++) {
            int id = tid + l * 256;
            int row = id >> 3, c = id & 7;
            uint32_t so = (uint32_t)(row * VP + c * 8) * 2;
            size_t g = rowbase + (size_t)(k0 + row) * D_MODEL + c * 8;
            cp16(st + so, khi + g);
            cp16(st + A_KVQ + so, klo + g);
            cp16(st + 2 * A_KVQ + so, vhi + g);
            cp16(st + 3 * A_KVQ + so, vlo + g);
        }
        CP_COMMIT();
    };

    // prologue: Q tile + KV stage 0 in one cp.async group
    #pragma unroll
    for (int l = 0; l < 4; l++) {
        int id = tid + l * 256;
        int row = id >> 3, c = id & 7;
        uint32_t so = (uint32_t)(row * VP + c * 8) * 2;
        size_t g = rowbase + (size_t)(q0 + row) * D_MODEL + c * 8;
        cp16(QH + so, qhi + g);
        cp16(QL + so, qlo + g);
    }
    {
        const uint32_t st = sb + 2 * A_QBYTES;
        #pragma unroll
        for (int l = 0; l < 2; l++) {
            int id = tid + l * 256;
            int row = id >> 3, c = id & 7;
            uint32_t so = (uint32_t)(row * VP + c * 8) * 2;
            size_t g = rowbase + (size_t)row * D_MODEL + c * 8;
            cp16(st + so, khi + g);
            cp16(st + A_KVQ + so, klo + g);
            cp16(st + 2 * A_KVQ + so, vhi + g);
            cp16(st + 3 * A_KVQ + so, vlo + g);
        }
        CP_COMMIT();
    }

    float m_i[2] = { -1e30f, -1e30f }, l_i[2] = { 0.f, 0.f };
    float o[8][4];
    #pragma unroll
    for (int j = 0; j < 8; j++)
        #pragma unroll
        for (int c = 0; c < 4; c++) o[j][c] = 0.f;

    for (int kt = 0; kt < SEQ / 64; kt++) {
        const int s = kt & 1;
        if (kt + 1 < SEQ / 64) { load_kv(kt + 1); CP_WAIT1(); } else { CP_WAIT0(); }
        __syncthreads();
        const uint32_t st = sb + 2 * A_QBYTES + s * A_STG;

        // ---- S = Q @ K^T  (16 q-rows per warp x 64 keys)
        float sf[8][4];
        #pragma unroll
        for (int j = 0; j < 8; j++)
            #pragma unroll
            for (int c = 0; c < 4; c++) sf[j][c] = 0.f;

        #pragma unroll
        for (int ks = 0; ks < 4; ks++) {
            uint32_t aq_hi[4], aq_lo[4];
            {
                int row = w * 16 + (L & 15);
                int col = ks * 16 + ((L >> 4) & 1) * 8;
                uint32_t off = (uint32_t)(row * VP + col) * 2;
                ldsm4(aq_hi, QH + off);
                ldsm4(aq_lo, QL + off);
            }
            #pragma unroll
            for (int p = 0; p < 4; p++) {
                int key = p * 16 + (L & 7) + ((L >> 4) & 1) * 8;
                int col = ks * 16 + ((L >> 3) & 1) * 8;
                uint32_t off = (uint32_t)(key * VP + col) * 2;
                uint32_t rh[4], rl[4];
                ldsm4(rh, st + off);
                ldsm4(rl, st + A_KVQ + off);
                uint32_t bh0[2] = { rh[0], rh[1] }, bh1[2] = { rh[2], rh[3] };
                uint32_t bl0[2] = { rl[0], rl[1] }, bl1[2] = { rl[2], rl[3] };
                mma_bf16(sf[2*p], aq_hi, bh0);
                mma_bf16(sf[2*p], aq_hi, bl0);
                mma_bf16(sf[2*p], aq_lo, bh0);
                mma_bf16(sf[2*p+1], aq_hi, bh1);
                mma_bf16(sf[2*p+1], aq_hi, bl1);
                mma_bf16(sf[2*p+1], aq_lo, bh1);
            }
        }

        // ---- online softmax (c-frag rows: L>>2 and +8; quad lanes share rows)
        #pragma unroll
        for (int r = 0; r < 2; r++) {
            float mloc = -1e30f;
            #pragma unroll
            for (int j = 0; j < 8; j++)
                mloc = fmaxf(mloc, fmaxf(sf[j][2*r], sf[j][2*r+1]));
            mloc = fmaxf(mloc, __shfl_xor_sync(0xffffffffu, mloc, 1));
            mloc = fmaxf(mloc, __shfl_xor_sync(0xffffffffu, mloc, 2));
            float mnew = fmaxf(m_i[r], mloc);
            float alpha = __expf(m_i[r] - mnew);
            float rs = 0.f;
            #pragma unroll
            for (int j = 0; j < 8; j++) {
                float p0 = __expf(sf[j][2*r] - mnew);
                float p1 = __expf(sf[j][2*r+1] - mnew);
                sf[j][2*r] = p0; sf[j][2*r+1] = p1;
                rs += p0 + p1;
            }
            rs += __shfl_xor_sync(0xffffffffu, rs, 1);
            rs += __shfl_xor_sync(0xffffffffu, rs, 2);
            l_i[r] = alpha * l_i[r] + rs;
            m_i[r] = mnew;
            #pragma unroll
            for (int j = 0; j < 8; j++) { o[j][2*r] *= alpha; o[j][2*r+1] *= alpha; }
        }

        // ---- pack P into A-fragments (C layout == A layout), bf16 split
        uint32_t ph[4][4], pl[4][4];
        #pragma unroll
        for (int q = 0; q < 4; q++) {
            ph[q][0] = pack_split(sf[2*q][0],   sf[2*q][1],   pl[q][0]);
            ph[q][1] = pack_split(sf[2*q][2],   sf[2*q][3],   pl[q][1]);
            ph[q][2] = pack_split(sf[2*q+1][0], sf[2*q+1][1], pl[q][2]);
            ph[q][3] = pack_split(sf[2*q+1][2], sf[2*q+1][3], pl[q][3]);
        }

        // ---- O += P @ V  (V via ldmatrix.trans: b-frags over (keys, d))
        #pragma unroll
        for (int q = 0; q < 4; q++) {
            #pragma unroll
            for (int dp = 0; dp < 4; dp++) {
                int key = q * 16 + (L & 15);
                int d = dp * 16 + ((L >> 4) & 1) * 8;
                uint32_t off = (uint32_t)(key * VP + d) * 2;
                uint32_t rh[4], rl[4];
                ldsm4t(rh, st + 2 * A_KVQ + off);
                ldsm4t(rl, st + 3 * A_KVQ + off);
                uint32_t vh0[2] = { rh[0], rh[1] }, vh1[2] = { rh[2], rh[3] };
                uint32_t vl0[2] = { rl[0], rl[1] }, vl1[2] = { rl[2], rl[3] };
                mma_bf16(o[2*dp], ph[q], vh0);
                mma_bf16(o[2*dp], ph[q], vl0);
                mma_bf16(o[2*dp], pl[q], vh0);
                mma_bf16(o[2*dp+1], ph[q], vh1);
                mma_bf16(o[2*dp+1], ph[q], vl1);
                mma_bf16(o[2*dp+1], pl[q], vh1);
            }
        }
        __syncthreads();
    }

    // ---- epilogue: normalize, fp32 write
    const float inv0 = 1.0f / l_i[0], inv1 = 1.0f / l_i[1];
    const int rg = q0 + w * 16 + (L >> 2);
    #pragma unroll
    for (int j = 0; j < 8; j++) {
        int col = j * 8 + 2 * (L & 3);
        float2 v0 = { o[j][0] * inv0, o[j][1] * inv0 };
        float2 v1 = { o[j][2] * inv1, o[j][3] * inv1 };
        *reinterpret_cast<float2*>(&O[rowbase + (size_t)rg * D_MODEL + col]) = v0;
        *reinterpret_cast<float2*>(&O[rowbase + (size_t)(rg + 8) * D_MODEL + col]) = v1;
    }
}

// ---------------------------------------------------------------------------
extern "C" void kernel_launch(void* const* d_in, const int* in_sizes, int n_in,
                              void* d_out, int out_size)
{
    const float* x  = (const float*)d_in[0];
    const float* Wq = (const float*)d_in[1];
    const float* bq = (const float*)d_in[2];
    const float* Wk = (const float*)d_in[3];
    const float* bk = (const float*)d_in[4];
    const float* Wv = (const float*)d_in[5];
    const float* bv = (const float*)d_in[6];
    const float* Wo = (const float*)d_in[7];
    const float* bo = (const float*)d_in[8];
    float* out = (float*)d_out;

    float *Qp, *Kp, *Vp, *Op;
    bf16 *xhi, *xlo, *aohi, *aolo, *whi, *wlo, *qhi, *qlo, *khi, *klo, *vhi, *vlo;
    cudaGetSymbolAddress((void**)&Qp, g_Q);
    cudaGetSymbolAddress((void**)&Kp, g_K);
    cudaGetSymbolAddress((void**)&Vp, g_V);
    cudaGetSymbolAddress((void**)&Op, g_AO);
    cudaGetSymbolAddress((void**)&xhi, g_xhi);
    cudaGetSymbolAddress((void**)&xlo, g_xlo);
    cudaGetSymbolAddress((void**)&aohi, g_aohi);
    cudaGetSymbolAddress((void**)&aolo, g_aolo);
    cudaGetSymbolAddress((void**)&whi, g_whi);
    cudaGetSymbolAddress((void**)&wlo, g_wlo);
    cudaGetSymbolAddress((void**)&qhi, g_qhi);
    cudaGetSymbolAddress((void**)&qlo, g_qlo);
    cudaGetSymbolAddress((void**)&khi, g_khi);
    cudaGetSymbolAddress((void**)&klo, g_klo);
    cudaGetSymbolAddress((void**)&vhi, g_vhi);
    cudaGetSymbolAddress((void**)&vlo, g_vlo);

    cudaFuncSetAttribute(gemm_tc, cudaFuncAttributeMaxDynamicSharedMemorySize, G_SMEM);
    cudaFuncSetAttribute(attn_tc, cudaFuncAttributeMaxDynamicSharedMemorySize, A_SMEM);

    const int nx4 = MTOT * D_MODEL / 4;
    const int nw4 = D_MODEL * D_MODEL / 4;
    dim3 ggrid(D_MODEL / 128, MTOT / 128);   // (8, 32)

    // split input activations once
    split_kernel<<<nx4 / 256, 256>>>(x, xhi, xlo, nx4, 1.0f);

    // Q/K/V projections on tensor cores (fp32 outputs; validated)
    split_kernel<<<nw4 / 256, 256>>>(Wq, whi, wlo, nw4, 1.0f);
    gemm_tc<<<ggrid, 256, G_SMEM>>>(xhi, xlo, whi, wlo, bq, Qp);
    split_kernel<<<nw4 / 256, 256>>>(Wk, whi, wlo, nw4, 1.0f);
    gemm_tc<<<ggrid, 256, G_SMEM>>>(xhi, xlo, whi, wlo, bk, Kp);
    split_kernel<<<nw4 / 256, 256>>>(Wv, whi, wlo, nw4, 1.0f);
    gemm_tc<<<ggrid, 256, G_SMEM>>>(xhi, xlo, whi, wlo, bv, Vp);

    // split Q (with 1/sqrt(Dh) baked in), K, V for the mma attention
    split_kernel<<<nx4 / 256, 256>>>(Qp, qhi, qlo, nx4, 0.125f);
    split_kernel<<<nx4 / 256, 256>>>(Kp, khi, klo, nx4, 1.0f);
    split_kernel<<<nx4 / 256, 256>>>(Vp, vhi, vlo, nx4, 1.0f);

    // tensor-core flash attention
    dim3 agrid(SEQ / 128, BATCH * NUM_HEADS);  // (16, 32)
    attn_tc<<<agrid, 256, A_SMEM>>>(qhi, qlo, khi, klo, vhi, vlo, Op);

    // output projection on tensor cores
    split_kernel<<<nx4 / 256, 256>>>(Op, aohi, aolo, nx4, 1.0f);
    split_kernel<<<nw4 / 256, 256>>>(Wo, whi, wlo, nw4, 1.0f);
    gemm_tc<<<ggrid, 256, G_SMEM>>>(aohi, aolo, whi, wlo, bo, out);
}